// round 11
// baseline (speedup 1.0000x reference)
#include <cuda_runtime.h>
#include <cuda_bf16.h>
#include <cstdint>
#include <math.h>

#define BATCH 8192
#define NC    2048
#define NF    512

#define BM 128
#define BN 256
#define BK 64          // bf16 elems per K-tile (128 bytes/row)
#define NT (NF / BK)   // 8 K-tiles
#define NSTAGE 3

// ---------------- device scratch (no allocs allowed) ----------------
__device__ float g_xsq[BATCH];
__device__ float g_csq[NC];
__device__ float g_inv2s[NC];
__device__ __nv_bfloat16 g_Abf[(size_t)BATCH * NF];
__device__ __nv_bfloat16 g_Bbf[(size_t)NC * NF];

// ---------------- portable PTX helpers (sm_80+ features only) ----------------
__device__ __forceinline__ uint32_t smem_u32(const void* p) {
    uint32_t a;
    asm("{ .reg .u64 t; cvta.to.shared.u64 t, %1; cvt.u32.u64 %0, t; }"
        : "=r"(a) : "l"(p));
    return a;
}

__device__ __forceinline__ void cp_async16(uint32_t dst, const void* src) {
    asm volatile("cp.async.cg.shared.global [%0], [%1], 16;"
                 :: "r"(dst), "l"(src) : "memory");
}
#define CP_COMMIT() asm volatile("cp.async.commit_group;" ::: "memory")
#define CP_WAIT_1() asm volatile("cp.async.wait_group 1;" ::: "memory")
#define CP_WAIT_0() asm volatile("cp.async.wait_group 0;" ::: "memory")

__device__ __forceinline__ void ldsm_x4(uint32_t* r, uint32_t addr) {
    asm volatile("ldmatrix.sync.aligned.m8n8.x4.shared.b16 {%0,%1,%2,%3}, [%4];"
                 : "=r"(r[0]), "=r"(r[1]), "=r"(r[2]), "=r"(r[3]) : "r"(addr));
}

__device__ __forceinline__ void mma_16816(float* c, const uint32_t* a,
                                          uint32_t b0, uint32_t b1) {
    asm volatile("mma.sync.aligned.m16n8k16.row.col.f32.bf16.bf16.f32 "
                 "{%0,%1,%2,%3}, {%4,%5,%6,%7}, {%8,%9}, {%0,%1,%2,%3};"
                 : "+f"(c[0]), "+f"(c[1]), "+f"(c[2]), "+f"(c[3])
                 : "r"(a[0]), "r"(a[1]), "r"(a[2]), "r"(a[3]), "r"(b0), "r"(b1));
}

// ---------------- SMEM layout (dynamic) ----------------
// stage s: A (16K) then B (32K); after all stages: xsq(512B), csq(1K), inv2s(1K)
static constexpr int A_BYTES = BM * 128;            // 16384
static constexpr int B_BYTES = BN * 128;            // 32768
static constexpr int STAGE_BYTES = A_BYTES + B_BYTES;   // 49152
static constexpr int OFF_STAGE0 = 1024;
static constexpr int OFF_XS = OFF_STAGE0 + NSTAGE * STAGE_BYTES;   // 148480
static constexpr int OFF_CS = OFF_XS + 512;
static constexpr int OFF_IS = OFF_CS + 1024;
static constexpr int SMEM_TOTAL = OFF_IS + 1024;    // 151552 bytes

// ---------------- merged prologue: converts + norms + sigma ----------------
// blocks [0, BATCH/8): A rows; [BATCH/8, (BATCH+NC)/8): B rows; sigma folded in.
__global__ void prologue_kernel(const float* __restrict__ A,
                                const float* __restrict__ B,
                                const float* __restrict__ sig,
                                __nv_bfloat16* __restrict__ Ab,
                                __nv_bfloat16* __restrict__ Bb,
                                float* __restrict__ xsq,
                                float* __restrict__ csq,
                                float* __restrict__ inv2s) {
    const int ablocks = BATCH / 8;
    int lane = threadIdx.x & 31;
    int wrow = blockIdx.x * 8 + (threadIdx.x >> 5);

    const float* X; __nv_bfloat16* Xb; float* nrm; int row;
    if (blockIdx.x < ablocks) { X = A; Xb = Ab; nrm = xsq; row = wrow; }
    else { X = B; Xb = Bb; nrm = csq; row = wrow - BATCH; }

    const float4* p = reinterpret_cast<const float4*>(X + (size_t)row * NF);
    __nv_bfloat162* q = reinterpret_cast<__nv_bfloat162*>(Xb + (size_t)row * NF);
    float s = 0.f;
    #pragma unroll
    for (int i = 0; i < NF / 4 / 32; i++) {
        int idx = lane + i * 32;
        float4 v = p[idx];
        s += v.x * v.x + v.y * v.y + v.z * v.z + v.w * v.w;
        q[idx * 2]     = __floats2bfloat162_rn(v.x, v.y);
        q[idx * 2 + 1] = __floats2bfloat162_rn(v.z, v.w);
    }
    #pragma unroll
    for (int o = 16; o; o >>= 1) s += __shfl_xor_sync(0xffffffffu, s, o);
    if (lane == 0) nrm[row] = s;

    // sigma: first NC/256 blocks also compute inv2s
    int si = blockIdx.x * blockDim.x + threadIdx.x;
    if (si < NC) {
        float sg = sig[si];
        inv2s[si] = 1.0f / (2.0f * sg * sg);
    }
}

// ---------------- HMMA GEMM 128x256, warp tile 64x64, fused RBF ----------------
__global__ __launch_bounds__(256)
void rbf_mma_kernel(const __nv_bfloat16* __restrict__ Abf,
                    const __nv_bfloat16* __restrict__ Bbf,
                    const float* __restrict__ xsq,
                    const float* __restrict__ csq,
                    const float* __restrict__ inv2s,
                    float* __restrict__ C) {
    extern __shared__ char smem[];
    const uint32_t sb = smem_u32(smem);
    const int tid = threadIdx.x;
    const int wid = tid >> 5;
    const int lid = tid & 31;
    const int bx = blockIdx.x;           // N tile (BN=256)
    const int by = blockIdx.y;           // M tile (BM=128)
    const int warp_m = wid & 1;          // 2 m-warps * 64 rows
    const int warp_n = wid >> 1;         // 4 n-warps * 64 cols

    // stage per-tile xsq / csq / inv2s
    if (tid < 128) reinterpret_cast<float*>(smem + OFF_XS)[tid] = xsq[by * BM + tid];
    reinterpret_cast<float*>(smem + OFF_CS)[tid] = csq[bx * BN + tid];
    reinterpret_cast<float*>(smem + OFF_IS)[tid] = inv2s[bx * BN + tid];

    const __nv_bfloat16* Ag0 = Abf + (size_t)(by * BM) * NF;
    const __nv_bfloat16* Bg0 = Bbf + (size_t)(bx * BN) * NF;

    const int ld_row0 = tid >> 3;        // 0..31
    const int ld_c16  = tid & 7;         // 16B chunk in 128B row

    auto load_tile = [&](int kt, int stage) {
        const uint32_t offA = OFF_STAGE0 + stage * STAGE_BYTES;
        const uint32_t offB = offA + A_BYTES;
        const int k0 = kt * BK;
        #pragma unroll
        for (int i = 0; i < 4; i++) {    // A: 128 rows
            int row = ld_row0 + i * 32;
            uint32_t sw = (uint32_t)row * 128 + ((uint32_t)(ld_c16 ^ (row & 7)) << 4);
            cp_async16(sb + offA + sw, Ag0 + (size_t)row * NF + k0 + ld_c16 * 8);
        }
        #pragma unroll
        for (int i = 0; i < 8; i++) {    // B: 256 rows
            int row = ld_row0 + i * 32;
            uint32_t sw = (uint32_t)row * 128 + ((uint32_t)(ld_c16 ^ (row & 7)) << 4);
            cp_async16(sb + offB + sw, Bg0 + (size_t)row * NF + k0 + ld_c16 * 8);
        }
    };

    // ldmatrix lane geometry: row = frag_base + (lid&15), chunk = s*2 + (lid>>4)
    const int lrow = lid & 15;
    const int lchk = lid >> 4;
    const int rowA0 = warp_m * 64 + lrow;          // mi adds 16 each
    const int rowB0 = warp_n * 64 + lrow;          // nq adds 16 each
    const uint32_t xA = (uint32_t)(rowA0 & 7);     // +16 keeps low 3 bits
    const uint32_t xB = (uint32_t)(rowB0 & 7);
    const uint32_t rA_off0 = (uint32_t)rowA0 * 128;
    const uint32_t rB_off0 = (uint32_t)rowB0 * 128;

    float acc[4][8][4];
    #pragma unroll
    for (int mi = 0; mi < 4; mi++)
        #pragma unroll
        for (int n = 0; n < 8; n++)
            #pragma unroll
            for (int v = 0; v < 4; v++) acc[mi][n][v] = 0.f;

    load_tile(0, 0); CP_COMMIT();
    load_tile(1, 1); CP_COMMIT();

    for (int t = 0; t < NT; t++) {
        if (t == NT - 1) { CP_WAIT_0(); } else { CP_WAIT_1(); }
        __syncthreads();
        if (t + 2 < NT) { load_tile(t + 2, (t + 2) % NSTAGE); CP_COMMIT(); }

        const uint32_t baseA = sb + OFF_STAGE0 + (t % NSTAGE) * STAGE_BYTES;
        const uint32_t baseB = baseA + A_BYTES;

        #pragma unroll
        for (int s = 0; s < BK / 16; s++) {        // 4 k16-steps
            const uint32_t cc = (uint32_t)(s * 2 + lchk);
            const uint32_t swA = ((cc ^ xA) & 7) << 4;
            const uint32_t swB = ((cc ^ xB) & 7) << 4;
            uint32_t a[4][4];
            #pragma unroll
            for (int mi = 0; mi < 4; mi++)
                ldsm_x4(a[mi], baseA + rA_off0 + mi * 2048 + swA);
            uint32_t b[4][4];
            #pragma unroll
            for (int nq = 0; nq < 4; nq++)
                ldsm_x4(b[nq], baseB + rB_off0 + nq * 2048 + swB);
            #pragma unroll
            for (int mi = 0; mi < 4; mi++)
                #pragma unroll
                for (int nq = 0; nq < 4; nq++) {
                    mma_16816(acc[mi][nq * 2 + 0], a[mi], b[nq][0], b[nq][2]);
                    mma_16816(acc[mi][nq * 2 + 1], a[mi], b[nq][1], b[nq][3]);
                }
        }
    }

    // ---------------- fused RBF epilogue ----------------
    const float* xs = reinterpret_cast<const float*>(smem + OFF_XS);
    const float* cs = reinterpret_cast<const float*>(smem + OFF_CS) + warp_n * 64;
    const float* is = reinterpret_cast<const float*>(smem + OFF_IS) + warp_n * 64;
    const int l4 = lid >> 2;
    const int l2 = (lid & 3) * 2;

    #pragma unroll
    for (int mi = 0; mi < 4; mi++) {
        #pragma unroll
        for (int h = 0; h < 2; h++) {
            const int r = warp_m * 64 + mi * 16 + h * 8 + l4;
            const float xm = xs[r];
            float* crow = C + (size_t)(by * BM + r) * NC + bx * BN + warp_n * 64;
            #pragma unroll
            for (int n = 0; n < 8; n++) {
                const int cidx = n * 8 + l2;
                float d0 = fmaf(-2.0f, acc[mi][n][h * 2 + 0], xm + cs[cidx]);
                float d1 = fmaf(-2.0f, acc[mi][n][h * 2 + 1], xm + cs[cidx + 1]);
                float2 o;
                o.x = __expf(-fmaxf(d0, 0.0f) * is[cidx]);
                o.y = __expf(-fmaxf(d1, 0.0f) * is[cidx + 1]);
                *reinterpret_cast<float2*>(crow + cidx) = o;
            }
        }
    }
}

// ---------------- launch ----------------
extern "C" void kernel_launch(void* const* d_in, const int* in_sizes, int n_in,
                              void* d_out, int out_size) {
    const float* inputs  = (const float*)d_in[0];
    const float* centers = (const float*)d_in[1];
    const float* sigmas  = (const float*)d_in[2];
    float* out = (float*)d_out;

    float *xsq, *csq, *inv2s;
    __nv_bfloat16 *Abf, *Bbf;
    cudaGetSymbolAddress((void**)&xsq,   g_xsq);
    cudaGetSymbolAddress((void**)&csq,   g_csq);
    cudaGetSymbolAddress((void**)&inv2s, g_inv2s);
    cudaGetSymbolAddress((void**)&Abf,   g_Abf);
    cudaGetSymbolAddress((void**)&Bbf,   g_Bbf);

    cudaFuncSetAttribute(rbf_mma_kernel,
                         cudaFuncAttributeMaxDynamicSharedMemorySize, SMEM_TOTAL);

    prologue_kernel<<<(BATCH + NC) / 8, 256>>>(inputs, centers, sigmas,
                                               Abf, Bbf, xsq, csq, inv2s);

    dim3 grid(NC / BN, BATCH / BM);   // (8, 64)
    rbf_mma_kernel<<<grid, 256, SMEM_TOTAL>>>(Abf, Bbf, xsq, csq, inv2s, out);
}

// round 13
// speedup vs baseline: 1.2495x; 1.2495x over previous
#include <cuda_runtime.h>
#include <cuda_bf16.h>
#include <cstdint>
#include <math.h>

#define BATCH 8192
#define NC    2048
#define NF    512

#define BM 128
#define BN 128
#define BK 64          // bf16 elems per K-tile (128 bytes/row)
#define NT (NF / BK)   // 8 K-tiles
#define NSTAGE 3

// ---------------- device scratch (no allocs allowed) ----------------
__device__ float g_xsq[BATCH];
__device__ float g_csq[NC];
__device__ float g_inv2s[NC];
__device__ __nv_bfloat16 g_Abf[(size_t)BATCH * NF];
__device__ __nv_bfloat16 g_Bbf[(size_t)NC * NF];

// ---------------- portable PTX helpers (sm_80+ features only) ----------------
__device__ __forceinline__ uint32_t smem_u32(const void* p) {
    uint32_t a;
    asm("{ .reg .u64 t; cvta.to.shared.u64 t, %1; cvt.u32.u64 %0, t; }"
        : "=r"(a) : "l"(p));
    return a;
}

__device__ __forceinline__ void cp_async16(uint32_t dst, const void* src) {
    asm volatile("cp.async.cg.shared.global [%0], [%1], 16;"
                 :: "r"(dst), "l"(src) : "memory");
}
#define CP_COMMIT() asm volatile("cp.async.commit_group;" ::: "memory")
#define CP_WAIT_1() asm volatile("cp.async.wait_group 1;" ::: "memory")
#define CP_WAIT_0() asm volatile("cp.async.wait_group 0;" ::: "memory")

__device__ __forceinline__ void ldsm_x4(uint32_t* r, uint32_t addr) {
    asm volatile("ldmatrix.sync.aligned.m8n8.x4.shared.b16 {%0,%1,%2,%3}, [%4];"
                 : "=r"(r[0]), "=r"(r[1]), "=r"(r[2]), "=r"(r[3]) : "r"(addr));
}

__device__ __forceinline__ void mma_16816(float* c, const uint32_t* a,
                                          uint32_t b0, uint32_t b1) {
    asm volatile("mma.sync.aligned.m16n8k16.row.col.f32.bf16.bf16.f32 "
                 "{%0,%1,%2,%3}, {%4,%5,%6,%7}, {%8,%9}, {%0,%1,%2,%3};"
                 : "+f"(c[0]), "+f"(c[1]), "+f"(c[2]), "+f"(c[3])
                 : "r"(a[0]), "r"(a[1]), "r"(a[2]), "r"(a[3]), "r"(b0), "r"(b1));
}

// ---------------- SMEM layout (dynamic) ----------------
static constexpr int A_BYTES = BM * 128;                 // 16384
static constexpr int B_BYTES = BN * 128;                 // 16384
static constexpr int STAGE_BYTES = A_BYTES + B_BYTES;    // 32768
static constexpr int OFF_STAGE0 = 0;
static constexpr int OFF_XS = OFF_STAGE0 + NSTAGE * STAGE_BYTES;  // 98304
static constexpr int OFF_CS = OFF_XS + 512;
static constexpr int OFF_IS = OFF_CS + 512;
static constexpr int SMEM_TOTAL = OFF_IS + 512;          // 99840 bytes

// ---------------- merged prologue: converts + norms + sigma ----------------
__global__ void prologue_kernel(const float* __restrict__ A,
                                const float* __restrict__ B,
                                const float* __restrict__ sig,
                                __nv_bfloat16* __restrict__ Ab,
                                __nv_bfloat16* __restrict__ Bb,
                                float* __restrict__ xsq,
                                float* __restrict__ csq,
                                float* __restrict__ inv2s) {
    const int ablocks = BATCH / 8;
    int lane = threadIdx.x & 31;
    int wrow = blockIdx.x * 8 + (threadIdx.x >> 5);

    const float* X; __nv_bfloat16* Xb; float* nrm; int row;
    if (blockIdx.x < ablocks) { X = A; Xb = Ab; nrm = xsq; row = wrow; }
    else { X = B; Xb = Bb; nrm = csq; row = wrow - BATCH; }

    const float4* p = reinterpret_cast<const float4*>(X + (size_t)row * NF);
    __nv_bfloat162* q = reinterpret_cast<__nv_bfloat162*>(Xb + (size_t)row * NF);
    float s = 0.f;
    #pragma unroll
    for (int i = 0; i < NF / 4 / 32; i++) {
        int idx = lane + i * 32;
        float4 v = p[idx];
        s += v.x * v.x + v.y * v.y + v.z * v.z + v.w * v.w;
        q[idx * 2]     = __floats2bfloat162_rn(v.x, v.y);
        q[idx * 2 + 1] = __floats2bfloat162_rn(v.z, v.w);
    }
    #pragma unroll
    for (int o = 16; o; o >>= 1) s += __shfl_xor_sync(0xffffffffu, s, o);
    if (lane == 0) nrm[row] = s;

    int si = blockIdx.x * blockDim.x + threadIdx.x;
    if (si < NC) {
        float sg = sig[si];
        inv2s[si] = 1.0f / (2.0f * sg * sg);
    }
}

// ---------------- HMMA GEMM 128x128, warp 32x64, k-pipelined frags ----------------
__global__ __launch_bounds__(256, 2)
void rbf_mma_kernel(const __nv_bfloat16* __restrict__ Abf,
                    const __nv_bfloat16* __restrict__ Bbf,
                    const float* __restrict__ xsq,
                    const float* __restrict__ csq,
                    const float* __restrict__ inv2s,
                    float* __restrict__ C) {
    extern __shared__ char smem[];
    const uint32_t sb = smem_u32(smem);
    const int tid = threadIdx.x;
    const int wid = tid >> 5;
    const int lid = tid & 31;
    const int bx = blockIdx.x;           // N tile
    const int by = blockIdx.y;           // M tile
    const int warp_m = wid & 3;          // 4 m-warps * 32 rows
    const int warp_n = wid >> 2;         // 2 n-warps * 64 cols

    if (tid < 128) {
        reinterpret_cast<float*>(smem + OFF_XS)[tid] = xsq[by * BM + tid];
        reinterpret_cast<float*>(smem + OFF_CS)[tid] = csq[bx * BN + tid];
        reinterpret_cast<float*>(smem + OFF_IS)[tid] = inv2s[bx * BN + tid];
    }

    // ---- cp.async addressing, all invariants hoisted ----
    const int ld_row0 = tid >> 3;        // 0..31
    const int ld_c16  = tid & 7;
    // per-thread global base (element offset): row*NF + c16*8; advance by BK per tile
    const __nv_bfloat16* agp[4];
    const __nv_bfloat16* bgp[4];
    uint32_t sdst[4];                    // swizzled smem offset within a stage (A); B adds A_BYTES
    #pragma unroll
    for (int i = 0; i < 4; i++) {
        int row = ld_row0 + i * 32;
        agp[i] = Abf + (size_t)(by * BM + row) * NF + ld_c16 * 8;
        bgp[i] = Bbf + (size_t)(bx * BN + row) * NF + ld_c16 * 8;
        sdst[i] = (uint32_t)row * 128 + ((uint32_t)(ld_c16 ^ (row & 7)) << 4);
    }

    auto load_tile = [&](int kt, int stage) {
        const uint32_t base = sb + OFF_STAGE0 + stage * STAGE_BYTES;
        const int k0 = kt * BK;
        #pragma unroll
        for (int i = 0; i < 4; i++) {
            cp_async16(base + sdst[i], agp[i] + k0);
            cp_async16(base + A_BYTES + sdst[i], bgp[i] + k0);
        }
    };

    // ---- ldmatrix lane geometry ----
    const int lrow = lid & 15;
    const int lchk = lid >> 4;
    const int rowA0 = warp_m * 32 + lrow;
    const int rowB0 = warp_n * 64 + lrow;
    const uint32_t xA = (uint32_t)(rowA0 & 7);
    const uint32_t xB = (uint32_t)(rowB0 & 7);
    const uint32_t rA_off0 = (uint32_t)rowA0 * 128;
    const uint32_t rB_off0 = (uint32_t)rowB0 * 128;

    float acc[2][8][4];
    #pragma unroll
    for (int mi = 0; mi < 2; mi++)
        #pragma unroll
        for (int n = 0; n < 8; n++)
            #pragma unroll
            for (int v = 0; v < 4; v++) acc[mi][n][v] = 0.f;

    load_tile(0, 0); CP_COMMIT();
    load_tile(1, 1); CP_COMMIT();

    uint32_t a[2][2][4];   // [buf][mi][frag]
    uint32_t b[2][4][4];   // [buf][nq][frag]

    for (int t = 0; t < NT; t++) {
        if (t == NT - 1) { CP_WAIT_0(); } else { CP_WAIT_1(); }
        __syncthreads();
        if (t + 2 < NT) { load_tile(t + 2, (t + 2) % NSTAGE); CP_COMMIT(); }

        const uint32_t baseA = sb + OFF_STAGE0 + (t % NSTAGE) * STAGE_BYTES;
        const uint32_t baseB = baseA + A_BYTES;

        // fragment-load for k16-step s into buffer bi
        auto ld_step = [&](int s, int bi) {
            const uint32_t cc = (uint32_t)(s * 2 + lchk);
            const uint32_t swA = ((cc ^ xA) & 7) << 4;
            const uint32_t swB = ((cc ^ xB) & 7) << 4;
            ldsm_x4(a[bi][0], baseA + rA_off0 + swA);
            ldsm_x4(a[bi][1], baseA + rA_off0 + 2048 + swA);
            #pragma unroll
            for (int nq = 0; nq < 4; nq++)
                ldsm_x4(b[bi][nq], baseB + rB_off0 + nq * 2048 + swB);
        };

        ld_step(0, 0);
        #pragma unroll
        for (int s = 0; s < BK / 16; s++) {
            const int cur = s & 1, nxt = cur ^ 1;
            if (s + 1 < BK / 16) ld_step(s + 1, nxt);   // prefetch next step
            #pragma unroll
            for (int mi = 0; mi < 2; mi++)
                #pragma unroll
                for (int nq = 0; nq < 4; nq++) {
                    mma_16816(acc[mi][nq * 2 + 0], a[cur][mi], b[cur][nq][0], b[cur][nq][2]);
                    mma_16816(acc[mi][nq * 2 + 1], a[cur][mi], b[cur][nq][1], b[cur][nq][3]);
                }
        }
    }

    // ---------------- fused RBF epilogue ----------------
    const float* xs = reinterpret_cast<const float*>(smem + OFF_XS);
    const float* cs = reinterpret_cast<const float*>(smem + OFF_CS) + warp_n * 64;
    const float* is = reinterpret_cast<const float*>(smem + OFF_IS) + warp_n * 64;
    const int l4 = lid >> 2;
    const int l2 = (lid & 3) * 2;

    #pragma unroll
    for (int mi = 0; mi < 2; mi++) {
        #pragma unroll
        for (int h = 0; h < 2; h++) {
            const int r = warp_m * 32 + mi * 16 + h * 8 + l4;
            const float xm = xs[r];
            float* crow = C + (size_t)(by * BM + r) * NC + bx * BN + warp_n * 64;
            #pragma unroll
            for (int n = 0; n < 8; n++) {
                const int cidx = n * 8 + l2;
                float d0 = fmaf(-2.0f, acc[mi][n][h * 2 + 0], xm + cs[cidx]);
                float d1 = fmaf(-2.0f, acc[mi][n][h * 2 + 1], xm + cs[cidx + 1]);
                float2 o;
                o.x = __expf(-fmaxf(d0, 0.0f) * is[cidx]);
                o.y = __expf(-fmaxf(d1, 0.0f) * is[cidx + 1]);
                *reinterpret_cast<float2*>(crow + cidx) = o;
            }
        }
    }
}

// ---------------- launch ----------------
extern "C" void kernel_launch(void* const* d_in, const int* in_sizes, int n_in,
                              void* d_out, int out_size) {
    const float* inputs  = (const float*)d_in[0];
    const float* centers = (const float*)d_in[1];
    const float* sigmas  = (const float*)d_in[2];
    float* out = (float*)d_out;

    float *xsq, *csq, *inv2s;
    __nv_bfloat16 *Abf, *Bbf;
    cudaGetSymbolAddress((void**)&xsq,   g_xsq);
    cudaGetSymbolAddress((void**)&csq,   g_csq);
    cudaGetSymbolAddress((void**)&inv2s, g_inv2s);
    cudaGetSymbolAddress((void**)&Abf,   g_Abf);
    cudaGetSymbolAddress((void**)&Bbf,   g_Bbf);

    cudaFuncSetAttribute(rbf_mma_kernel,
                         cudaFuncAttributeMaxDynamicSharedMemorySize, SMEM_TOTAL);

    prologue_kernel<<<(BATCH + NC) / 8, 256>>>(inputs, centers, sigmas,
                                               Abf, Bbf, xsq, csq, inv2s);

    dim3 grid(NC / BN, BATCH / BM);   // (16, 64)
    rbf_mma_kernel<<<grid, 256, SMEM_TOTAL>>>(Abf, Bbf, xsq, csq, inv2s, out);
}

// round 14
// speedup vs baseline: 1.2602x; 1.0086x over previous
#include <cuda_runtime.h>
#include <cuda_bf16.h>
#include <cstdint>
#include <math.h>

#define BATCH 8192
#define NC    2048
#define NF    512

#define BM 128
#define BN 128
#define BK 64          // bf16 elems per K-tile (128 bytes/row)
#define NT (NF / BK)   // 8 K-tiles
#define NSTAGE 3

// ---------------- device scratch (no allocs allowed) ----------------
__device__ float g_xsq[BATCH];
__device__ float g_csq[NC];
__device__ float g_inv2s[NC];
__device__ __nv_bfloat16 g_Abf[(size_t)BATCH * NF];
__device__ __nv_bfloat16 g_Bbf[(size_t)NC * NF];

// ---------------- portable PTX helpers (sm_80+ features only) ----------------
__device__ __forceinline__ uint32_t smem_u32(const void* p) {
    uint32_t a;
    asm("{ .reg .u64 t; cvta.to.shared.u64 t, %1; cvt.u32.u64 %0, t; }"
        : "=r"(a) : "l"(p));
    return a;
}

__device__ __forceinline__ void cp_async16(uint32_t dst, const void* src) {
    asm volatile("cp.async.cg.shared.global [%0], [%1], 16;"
                 :: "r"(dst), "l"(src) : "memory");
}
#define CP_COMMIT() asm volatile("cp.async.commit_group;" ::: "memory")
#define CP_WAIT_1() asm volatile("cp.async.wait_group 1;" ::: "memory")
#define CP_WAIT_0() asm volatile("cp.async.wait_group 0;" ::: "memory")

__device__ __forceinline__ void ldsm_x4(uint32_t* r, uint32_t addr) {
    asm volatile("ldmatrix.sync.aligned.m8n8.x4.shared.b16 {%0,%1,%2,%3}, [%4];"
                 : "=r"(r[0]), "=r"(r[1]), "=r"(r[2]), "=r"(r[3]) : "r"(addr));
}

__device__ __forceinline__ void mma_16816(float* c, const uint32_t* a,
                                          uint32_t b0, uint32_t b1) {
    asm volatile("mma.sync.aligned.m16n8k16.row.col.f32.bf16.bf16.f32 "
                 "{%0,%1,%2,%3}, {%4,%5,%6,%7}, {%8,%9}, {%0,%1,%2,%3};"
                 : "+f"(c[0]), "+f"(c[1]), "+f"(c[2]), "+f"(c[3])
                 : "r"(a[0]), "r"(a[1]), "r"(a[2]), "r"(a[3]), "r"(b0), "r"(b1));
}

// ---------------- SMEM layout (dynamic) ----------------
static constexpr int A_BYTES = BM * 128;                 // 16384
static constexpr int B_BYTES = BN * 128;                 // 16384
static constexpr int STAGE_BYTES = A_BYTES + B_BYTES;    // 32768
static constexpr int OFF_STAGE0 = 0;
static constexpr int OFF_XS = OFF_STAGE0 + NSTAGE * STAGE_BYTES;  // 98304
static constexpr int OFF_CS = OFF_XS + 512;
static constexpr int OFF_IS = OFF_CS + 512;
static constexpr int SMEM_TOTAL = OFF_IS + 512;          // 99840 bytes

// ---------------- merged prologue: converts + norms + sigma ----------------
__global__ void prologue_kernel(const float* __restrict__ A,
                                const float* __restrict__ B,
                                const float* __restrict__ sig,
                                __nv_bfloat16* __restrict__ Ab,
                                __nv_bfloat16* __restrict__ Bb,
                                float* __restrict__ xsq,
                                float* __restrict__ csq,
                                float* __restrict__ inv2s) {
    const int ablocks = BATCH / 8;
    int lane = threadIdx.x & 31;
    int wrow = blockIdx.x * 8 + (threadIdx.x >> 5);

    const float* X; __nv_bfloat16* Xb; float* nrm; int row;
    if (blockIdx.x < ablocks) { X = A; Xb = Ab; nrm = xsq; row = wrow; }
    else { X = B; Xb = Bb; nrm = csq; row = wrow - BATCH; }

    const float4* p = reinterpret_cast<const float4*>(X + (size_t)row * NF);
    __nv_bfloat162* q = reinterpret_cast<__nv_bfloat162*>(Xb + (size_t)row * NF);
    float s = 0.f;
    #pragma unroll
    for (int i = 0; i < NF / 4 / 32; i++) {
        int idx = lane + i * 32;
        float4 v = p[idx];
        s += v.x * v.x + v.y * v.y + v.z * v.z + v.w * v.w;
        q[idx * 2]     = __floats2bfloat162_rn(v.x, v.y);
        q[idx * 2 + 1] = __floats2bfloat162_rn(v.z, v.w);
    }
    #pragma unroll
    for (int o = 16; o; o >>= 1) s += __shfl_xor_sync(0xffffffffu, s, o);
    if (lane == 0) nrm[row] = s;

    int si = blockIdx.x * blockDim.x + threadIdx.x;
    if (si < NC) {
        float sg = sig[si];
        inv2s[si] = 1.0f / (2.0f * sg * sg);
    }
}

// ---------------- HMMA GEMM 128x128, 4 warps of 64x64, fused RBF ----------------
__global__ __launch_bounds__(128, 2)
void rbf_mma_kernel(const __nv_bfloat16* __restrict__ Abf,
                    const __nv_bfloat16* __restrict__ Bbf,
                    const float* __restrict__ xsq,
                    const float* __restrict__ csq,
                    const float* __restrict__ inv2s,
                    float* __restrict__ C) {
    extern __shared__ char smem[];
    const uint32_t sb = smem_u32(smem);
    const int tid = threadIdx.x;
    const int wid = tid >> 5;
    const int lid = tid & 31;
    const int bx = blockIdx.x;           // N tile
    const int by = blockIdx.y;           // M tile
    const int warp_m = wid & 1;          // 2 m-warps * 64 rows
    const int warp_n = wid >> 1;         // 2 n-warps * 64 cols

    // stage per-tile xsq / csq / inv2s (128 entries each; all 128 threads)
    reinterpret_cast<float*>(smem + OFF_XS)[tid] = xsq[by * BM + tid];
    reinterpret_cast<float*>(smem + OFF_CS)[tid] = csq[bx * BN + tid];
    reinterpret_cast<float*>(smem + OFF_IS)[tid] = inv2s[bx * BN + tid];

    // ---- cp.async addressing: one base + immediate offsets ----
    const int ld_row0 = tid >> 3;        // 0..15
    const int ld_c16  = tid & 7;
    const __nv_bfloat16* agp = Abf + (size_t)(by * BM + ld_row0) * NF + ld_c16 * 8;
    const __nv_bfloat16* bgp = Bbf + (size_t)(bx * BN + ld_row0) * NF + ld_c16 * 8;
    const uint32_t sdst0 = (uint32_t)ld_row0 * 128 +
                           ((uint32_t)(ld_c16 ^ (ld_row0 & 7)) << 4);

    auto load_tile = [&](int kt, int stage) {
        const uint32_t base = sb + OFF_STAGE0 + stage * STAGE_BYTES;
        const int k0 = kt * BK;
        #pragma unroll
        for (int i = 0; i < 8; i++) {    // rows ld_row0 + 16*i
            cp_async16(base + sdst0 + i * 2048, agp + k0 + (size_t)i * 16 * NF);
            cp_async16(base + A_BYTES + sdst0 + i * 2048, bgp + k0 + (size_t)i * 16 * NF);
        }
    };

    // ---- ldmatrix lane geometry ----
    const int lrow = lid & 15;
    const int lchk = lid >> 4;
    const int rowA0 = warp_m * 64 + lrow;          // mi adds 16 (keeps row&7)
    const int rowB0 = warp_n * 64 + lrow;
    const uint32_t xA = (uint32_t)(rowA0 & 7);
    const uint32_t xB = (uint32_t)(rowB0 & 7);
    const uint32_t rA_off0 = (uint32_t)rowA0 * 128;
    const uint32_t rB_off0 = (uint32_t)rowB0 * 128;

    // per-k16-step swizzled chunk offsets (t-invariant)
    uint32_t swA[4], swB[4];
    #pragma unroll
    for (int s = 0; s < 4; s++) {
        const uint32_t cc = (uint32_t)(s * 2 + lchk);
        swA[s] = ((cc ^ xA) & 7) << 4;
        swB[s] = ((cc ^ xB) & 7) << 4;
    }

    float acc[4][8][4];
    #pragma unroll
    for (int mi = 0; mi < 4; mi++)
        #pragma unroll
        for (int n = 0; n < 8; n++)
            #pragma unroll
            for (int v = 0; v < 4; v++) acc[mi][n][v] = 0.f;

    load_tile(0, 0); CP_COMMIT();
    load_tile(1, 1); CP_COMMIT();

    for (int t = 0; t < NT; t++) {
        if (t == NT - 1) { CP_WAIT_0(); } else { CP_WAIT_1(); }
        __syncthreads();
        if (t + 2 < NT) { load_tile(t + 2, (t + 2) % NSTAGE); CP_COMMIT(); }

        const uint32_t baseA = sb + OFF_STAGE0 + (t % NSTAGE) * STAGE_BYTES;
        const uint32_t baseB = baseA + A_BYTES;

        #pragma unroll
        for (int s = 0; s < BK / 16; s++) {
            uint32_t a[4][4], b[4][4];
            #pragma unroll
            for (int mi = 0; mi < 4; mi++)
                ldsm_x4(a[mi], baseA + rA_off0 + mi * 2048 + swA[s]);
            #pragma unroll
            for (int nq = 0; nq < 4; nq++)
                ldsm_x4(b[nq], baseB + rB_off0 + nq * 2048 + swB[s]);
            #pragma unroll
            for (int mi = 0; mi < 4; mi++)
                #pragma unroll
                for (int nq = 0; nq < 4; nq++) {
                    mma_16816(acc[mi][nq * 2 + 0], a[mi], b[nq][0], b[nq][2]);
                    mma_16816(acc[mi][nq * 2 + 1], a[mi], b[nq][1], b[nq][3]);
                }
        }
    }

    // ---------------- fused RBF epilogue ----------------
    const float* xs = reinterpret_cast<const float*>(smem + OFF_XS);
    const float* cs = reinterpret_cast<const float*>(smem + OFF_CS) + warp_n * 64;
    const float* is = reinterpret_cast<const float*>(smem + OFF_IS) + warp_n * 64;
    const int l4 = lid >> 2;
    const int l2 = (lid & 3) * 2;

    #pragma unroll
    for (int mi = 0; mi < 4; mi++) {
        #pragma unroll
        for (int h = 0; h < 2; h++) {
            const int r = warp_m * 64 + mi * 16 + h * 8 + l4;
            const float xm = xs[r];
            float* crow = C + (size_t)(by * BM + r) * NC + bx * BN + warp_n * 64;
            #pragma unroll
            for (int n = 0; n < 8; n++) {
                const int cidx = n * 8 + l2;
                float d0 = fmaf(-2.0f, acc[mi][n][h * 2 + 0], xm + cs[cidx]);
                float d1 = fmaf(-2.0f, acc[mi][n][h * 2 + 1], xm + cs[cidx + 1]);
                float2 o;
                o.x = __expf(-fmaxf(d0, 0.0f) * is[cidx]);
                o.y = __expf(-fmaxf(d1, 0.0f) * is[cidx + 1]);
                *reinterpret_cast<float2*>(crow + cidx) = o;
            }
        }
    }
}

// ---------------- launch ----------------
extern "C" void kernel_launch(void* const* d_in, const int* in_sizes, int n_in,
                              void* d_out, int out_size) {
    const float* inputs  = (const float*)d_in[0];
    const float* centers = (const float*)d_in[1];
    const float* sigmas  = (const float*)d_in[2];
    float* out = (float*)d_out;

    float *xsq, *csq, *inv2s;
    __nv_bfloat16 *Abf, *Bbf;
    cudaGetSymbolAddress((void**)&xsq,   g_xsq);
    cudaGetSymbolAddress((void**)&csq,   g_csq);
    cudaGetSymbolAddress((void**)&inv2s, g_inv2s);
    cudaGetSymbolAddress((void**)&Abf,   g_Abf);
    cudaGetSymbolAddress((void**)&Bbf,   g_Bbf);

    cudaFuncSetAttribute(rbf_mma_kernel,
                         cudaFuncAttributeMaxDynamicSharedMemorySize, SMEM_TOTAL);

    prologue_kernel<<<(BATCH + NC) / 8, 256>>>(inputs, centers, sigmas,
                                               Abf, Bbf, xsq, csq, inv2s);

    dim3 grid(NC / BN, BATCH / BM);   // (16, 64)
    rbf_mma_kernel<<<grid, 128, SMEM_TOTAL>>>(Abf, Bbf, xsq, csq, inv2s, out);
}